// round 10
// baseline (speedup 1.0000x reference)
#include <cuda_runtime.h>
#include <cstdint>

#define BB 2
#define PP 200000
#define QQ 100
#define TILE 128                       // points per tile
#define TPB  1563                      // tiles per batch = ceil(PP/TILE)
#define NT   (BB * TPB)                // 3126 tiles total
#define TILE_BYTES (TILE * QQ * 4)     // 51200 B per buffer
#define NCTA 296                       // 2 CTAs/SM * 148 SMs

__device__ int g_nonempty[BB][QQ];

__device__ __forceinline__ float fast_rcp(float d) {
    float r;
    asm("rcp.approx.f32 %0, %1;" : "=f"(r) : "f"(d));
    r = fmaf(fmaf(-d, r, 1.0f), r, r);
    return r;
}

// 16B-granule swizzle, applied identically at cp.async dst and gathered LDS.
__device__ __forceinline__ unsigned swz(unsigned byteoff) {
    return byteoff ^ ((byteoff >> 3) & 0x70u);
}

__global__ void zero_kernel() {
    int t = threadIdx.x;
    if (t < BB * QQ) ((int*)g_nonempty)[t] = 0;
}

// ---------------------------------------------------------------------------
// Persistent double-buffered main kernel. 296 CTAs x 128 threads.
// Prologue: compacted (kidx, score) tables for BOTH batches (ordered ballot
//   compaction; ties -> smallest query index, matching reference argmax).
// Loop over tiles (grid-stride): 2-stage cp.async pipeline; compute tile i
//   while tile i+stride streams into the other buffer.
// Compute per point: v = s*sigmoid(x) over kept queries only; running
//   max/argmax; unshifted softmax sum S' = sum exp(v); conf = exp(M)*rcp(S').
// Per-CTA nonempty flags accumulate across tiles; one atomicOr set at end.
// ---------------------------------------------------------------------------
__global__ void __launch_bounds__(TILE) main_kernel(
    const float* __restrict__ logits,
    const float* __restrict__ masks,
    const unsigned char* __restrict__ pad,
    float* __restrict__ out)
{
    extern __shared__ float s_x[];                 // 2 * TILE_BYTES, swizzled
    __shared__ __align__(16) int   kidx2[BB][112];
    __shared__ __align__(16) float ks2[BB][112];
    __shared__ int s_cnt[4];
    __shared__ int s_nk4[BB];
    __shared__ int flags2[BB][QQ];

    const int t = threadIdx.x;
    const int wid = t >> 5, lane = t & 31;
    const unsigned sbase = (unsigned)__cvta_generic_to_shared(s_x);

    // --- Prologue: keep/score tables for both batches, zero flags ---------
    if (t < QQ) { flags2[0][t] = 0; flags2[1][t] = 0; }
    #pragma unroll
    for (int b = 0; b < BB; b++) {
        bool kp = false; float sv = 0.0f;
        if (t < QQ) {
            float l0 = logits[(b * QQ + t) * 2 + 0];
            float l1 = logits[(b * QQ + t) * 2 + 1];
            sv = fmaxf(l0, l1);
            kp = !(l1 > l0);             // argmax first-tie -> label 0 (kept)
        }
        unsigned bal = __ballot_sync(0xffffffffu, kp);
        if (lane == 0) s_cnt[wid] = __popc(bal);
        __syncthreads();
        int woff = 0;
        #pragma unroll
        for (int w = 0; w < 4; w++) if (w < wid) woff += s_cnt[w];
        int nk  = s_cnt[0] + s_cnt[1] + s_cnt[2] + s_cnt[3];
        int nk4 = (nk + 3) & ~3;
        if (kp) {
            int pos = woff + __popc(bal & ((1u << lane) - 1u));
            kidx2[b][pos] = t; ks2[b][pos] = sv;
        }
        if (t < nk4 - nk) {              // pad: huge-negative v, exp -> 0
            kidx2[b][nk + t] = 0; ks2[b][nk + t] = -1e30f;
        }
        if (t == 0) s_nk4[b] = nk4 | (nk << 16);
        __syncthreads();
    }

    // --- Pipelined tile loop ----------------------------------------------
    const int i0 = blockIdx.x;
    // Prefetch first tile into buffer 0.
    if (i0 < NT) {
        int b = (i0 >= TPB) ? 1 : 0;
        int j = i0 - b * TPB;
        const char* gsrc = reinterpret_cast<const char*>(masks)
                         + ((size_t)b * PP + (size_t)j * TILE) * (QQ * 4);
        unsigned avail = (unsigned)(PP - j * TILE) * (QQ * 4);
        #pragma unroll
        for (int k = 0; k < 25; k++) {
            unsigned off = (unsigned)(k * TILE + t) * 16u;
            unsigned go = (off < avail) ? off : (avail - 16);
            asm volatile("cp.async.cg.shared.global [%0], [%1], 16;"
                         :: "r"(sbase + swz(off)), "l"(gsrc + go));
        }
    }
    asm volatile("cp.async.commit_group;");

    int cur = 0;
    for (int i = i0; i < NT; i += NCTA) {
        // Issue next tile into the other buffer.
        int inext = i + NCTA;
        if (inext < NT) {
            int bn = (inext >= TPB) ? 1 : 0;
            int jn = inext - bn * TPB;
            const char* gsrc = reinterpret_cast<const char*>(masks)
                             + ((size_t)bn * PP + (size_t)jn * TILE) * (QQ * 4);
            unsigned avail = (unsigned)(PP - jn * TILE) * (QQ * 4);
            unsigned nbase = sbase + (unsigned)(cur ^ 1) * TILE_BYTES;
            #pragma unroll
            for (int k = 0; k < 25; k++) {
                unsigned off = (unsigned)(k * TILE + t) * 16u;
                unsigned go = (off < avail) ? off : (avail - 16);
                asm volatile("cp.async.cg.shared.global [%0], [%1], 16;"
                             :: "r"(nbase + swz(off)), "l"(gsrc + go));
            }
        }
        asm volatile("cp.async.commit_group;");
        // Wait until only the newest group is pending -> current tile ready.
        asm volatile("cp.async.wait_group 1;" ::: "memory");
        __syncthreads();

        // ---- Compute current tile ----
        const int b = (i >= TPB) ? 1 : 0;
        const int j = i - b * TPB;
        const int p = j * TILE + t;
        const bool active = (p < PP);
        const int pc = active ? p : (PP - 1);
        const size_t gbase = (size_t)b * PP;
        const char* sbuf = reinterpret_cast<const char*>(s_x)
                         + (size_t)cur * TILE_BYTES;
        const unsigned rowb = (unsigned)t * (QQ * 4);
        const int nk4 = s_nk4[b] & 0xffff;
        const int nk  = s_nk4[b] >> 16;
        const int4*   k4 = reinterpret_cast<const int4*>(kidx2[b]);
        const float4* s4 = reinterpret_cast<const float4*>(ks2[b]);

        float M = -3.4e38f; int jm = 0;
        float S0 = 0.0f, S1 = 0.0f, S2 = 0.0f, S3 = 0.0f;

        for (int q4 = 0; q4 < (nk4 >> 2); q4++) {
            int4   ki = k4[q4];                        // broadcast LDS.128
            float4 ss = s4[q4];
            {   float x = *reinterpret_cast<const float*>(sbuf + swz(rowb + 4u * ki.x));
                float e = __expf(-fabsf(x));
                float num = (x < 0.0f) ? e : 1.0f;
                float sig = num * fast_rcp(1.0f + e);
                float v = ss.x * sig;
                S0 += __expf(v);
                if (v > M) { M = v; jm = 4 * q4 + 0; } }
            {   float x = *reinterpret_cast<const float*>(sbuf + swz(rowb + 4u * ki.y));
                float e = __expf(-fabsf(x));
                float num = (x < 0.0f) ? e : 1.0f;
                float sig = num * fast_rcp(1.0f + e);
                float v = ss.y * sig;
                S1 += __expf(v);
                if (v > M) { M = v; jm = 4 * q4 + 1; } }
            {   float x = *reinterpret_cast<const float*>(sbuf + swz(rowb + 4u * ki.z));
                float e = __expf(-fabsf(x));
                float num = (x < 0.0f) ? e : 1.0f;
                float sig = num * fast_rcp(1.0f + e);
                float v = ss.z * sig;
                S2 += __expf(v);
                if (v > M) { M = v; jm = 4 * q4 + 2; } }
            {   float x = *reinterpret_cast<const float*>(sbuf + swz(rowb + 4u * ki.w));
                float e = __expf(-fabsf(x));
                float num = (x < 0.0f) ? e : 1.0f;
                float sig = num * fast_rcp(1.0f + e);
                float v = ss.w * sig;
                S3 += __expf(v);
                if (v > M) { M = v; jm = 4 * q4 + 3; } }
        }
        float S = (S0 + S1) + (S2 + S3);

        int   mid  = kidx2[b][jm];
        float smid = ks2[b][jm];
        float sig_mid = M * fast_rcp(smid);
        bool validp = active && (nk > 0) && (sig_mid >= 1e-3f) &&
                      (pad[gbase + pc] == 0);

        if (validp) flags2[b][mid] = 1;   // benign race: same value

        if (active) {
            size_t base = gbase + p;
            out[base] = 0.0f;                                               // sem
            out[(size_t)BB * PP + base] = validp ? (float)(mid + 1) : 0.0f; // tmp
            out[(size_t)2 * BB * PP + base] = __expf(M) * fast_rcp(S);      // conf
        }

        __syncthreads();   // buffer reads done before it is refilled
        cur ^= 1;
    }

    // --- Flush per-CTA flags ----------------------------------------------
    if (t < QQ) {
        if (flags2[0][t]) atomicOr(&g_nonempty[0][t], 1);
        if (flags2[1][t]) atomicOr(&g_nonempty[1][t], 1);
    }
}

// ---------------------------------------------------------------------------
// Remap kernel: output float4 load issued FIRST (latency hidden by the scan),
// per-CTA Hillis-Steele scan of nonempty flags, float4 remap tmp -> seg_id.
// ---------------------------------------------------------------------------
__global__ void __launch_bounds__(256) remap_kernel(float* __restrict__ out) {
    __shared__ int sc[256];
    const int t = threadIdx.x;
    const int i = blockIdx.x * 256 + t;                // one float4 per thread
    const int i0 = i * 4;
    const bool act = (i0 < BB * PP);
    float4* p4 = reinterpret_cast<float4*>(out + (size_t)BB * PP) + i;
    float4 v = make_float4(0.f, 0.f, 0.f, 0.f);
    if (act) v = *p4;                                  // in flight during scan

    const int qb = (t < 100) ? t : t - 100;
    int val = 0;
    if (t < 200) val = (g_nonempty[t / 100][qb] != 0) ? 1 : 0;
    sc[t] = val;
    #pragma unroll
    for (int d = 1; d < 128; d <<= 1) {
        __syncthreads();
        int add = (t < 200 && qb >= d) ? sc[t - d] : 0;
        __syncthreads();
        sc[t] += add;
    }
    __syncthreads();

    if (act) {
        const int boff = (i0 >= PP) ? 100 : 0;         // PP % 4 == 0
        float r0 = v.x, r1 = v.y, r2 = v.z, r3 = v.w;
        if (r0 != 0.0f) r0 = (float)sc[boff + (int)r0 - 1];
        if (r1 != 0.0f) r1 = (float)sc[boff + (int)r1 - 1];
        if (r2 != 0.0f) r2 = (float)sc[boff + (int)r2 - 1];
        if (r3 != 0.0f) r3 = (float)sc[boff + (int)r3 - 1];
        *p4 = make_float4(r0, r1, r2, r3);
    }
}

extern "C" void kernel_launch(void* const* d_in, const int* in_sizes, int n_in,
                              void* d_out, int out_size) {
    const float* logits = (const float*)d_in[0];
    const float* masks  = (const float*)d_in[1];
    const unsigned char* pad = (const unsigned char*)d_in[2];
    float* out = (float*)d_out;

    static bool attr_set = false;
    if (!attr_set) {
        cudaFuncSetAttribute(main_kernel,
                             cudaFuncAttributeMaxDynamicSharedMemorySize,
                             2 * TILE_BYTES);
        attr_set = true;
    }

    zero_kernel<<<1, 256>>>();

    main_kernel<<<NCTA, TILE, 2 * TILE_BYTES>>>(logits, masks, pad, out);

    remap_kernel<<<(BB * PP / 4 + 255) / 256, 256>>>(out);
}

// round 12
// speedup vs baseline: 1.1746x; 1.1746x over previous
#include <cuda_runtime.h>
#include <cstdint>

#define BB 2
#define PP 200000
#define QQ 100
#define TILE 128          // points per CTA
#define TILE_BYTES (TILE * QQ * 4)   // 51200

// Per-batch nonempty bitmask: 4 words x 32 bits cover 100 queries.
__device__ unsigned g_bits[BB][4];

__device__ __forceinline__ float fast_rcp(float d) {
    float r;
    asm("rcp.approx.f32 %0, %1;" : "=f"(r) : "f"(d));
    r = fmaf(fmaf(-d, r, 1.0f), r, r);
    return r;
}

// 16B-granule swizzle, applied identically at cp.async dst and gathered LDS.
__device__ __forceinline__ unsigned swz(unsigned byteoff) {
    return byteoff ^ ((byteoff >> 3) & 0x70u);
}

// ---------------------------------------------------------------------------
// Main kernel (R8 one-shot shape: 4 CTAs/SM, cross-CTA load/compute overlap).
// A: cp.async.cg 16B chunks gmem -> swizzled smem tile (issued first).
// B: per-query keep/score; ORDERED ballot compaction (ties -> smallest idx).
// C: per-thread loop over kept queries; v = s*sigmoid(x); running max/argmax;
//    unshifted softmax sum S' = sum exp(v); conf = exp(M)*rcp(S').
// Epilogue: smem flags -> 4 ballot words -> 4 REDG atomicOr per CTA.
// ---------------------------------------------------------------------------
__global__ void __launch_bounds__(TILE) main_kernel(
    const float* __restrict__ logits,
    const float* __restrict__ masks,
    const unsigned char* __restrict__ pad,
    float* __restrict__ out)
{
    extern __shared__ float s_x[];                 // TILE*QQ floats, swizzled
    __shared__ __align__(16) int   kidx[112];
    __shared__ __align__(16) float ks[112];
    __shared__ int s_cnt[4];
    __shared__ int flags[QQ];

    const int t = threadIdx.x;
    const int b = blockIdx.y;
    const int tile0 = blockIdx.x * TILE;
    const size_t gbase = (size_t)b * PP;

    // --- Phase A: issue loads FIRST ---------------------------------------
    {
        const char* gsrc = reinterpret_cast<const char*>(masks)
                         + (gbase + (size_t)tile0) * (QQ * 4);
        unsigned sbase = (unsigned)__cvta_generic_to_shared(s_x);
        size_t avail = ((size_t)PP - tile0) * (QQ * 4);
        #pragma unroll
        for (int k = 0; k < 25; k++) {
            unsigned off = (unsigned)(k * TILE + t) * 16u;    // 0..51184
            unsigned so = sbase + swz(off);
            size_t go = (off < avail) ? (size_t)off : (avail - 16);
            asm volatile("cp.async.cg.shared.global [%0], [%1], 16;"
                         :: "r"(so), "l"(gsrc + go));
        }
        asm volatile("cp.async.commit_group;");
    }

    // --- Phase B: keep + ordered compaction (overlaps with loads) ---------
    if (t < QQ) flags[t] = 0;
    bool kp = false; float sv = 0.0f;
    if (t < QQ) {
        float l0 = logits[(b * QQ + t) * 2 + 0];
        float l1 = logits[(b * QQ + t) * 2 + 1];
        sv = fmaxf(l0, l1);
        kp = !(l1 > l0);                 // argmax first-tie -> label 0 (kept)
    }
    unsigned bal = __ballot_sync(0xffffffffu, kp);
    const int wid = t >> 5, lane = t & 31;
    if (lane == 0) s_cnt[wid] = __popc(bal);
    __syncthreads();
    int woff = 0;
    #pragma unroll
    for (int w = 0; w < 4; w++) if (w < wid) woff += s_cnt[w];
    const int nk  = s_cnt[0] + s_cnt[1] + s_cnt[2] + s_cnt[3];
    const int nk4 = (nk + 3) & ~3;
    if (kp) {
        int pos = woff + __popc(bal & ((1u << lane) - 1u));
        kidx[pos] = t; ks[pos] = sv;
    }
    if (t < nk4 - nk) {                  // pad: huge-negative v, exp -> 0
        kidx[nk + t] = 0; ks[nk + t] = -1e30f;
    }

    asm volatile("cp.async.wait_group 0;" ::: "memory");
    __syncthreads();

    // --- Phase C: compute --------------------------------------------------
    const int p = tile0 + t;
    const bool active = (p < PP);
    const int pc = active ? p : (PP - 1);
    const char* srow = reinterpret_cast<const char*>(s_x);
    const unsigned rowb = (unsigned)t * (QQ * 4);

    float M = -3.4e38f; int jm = 0;
    float S0 = 0.0f, S1 = 0.0f, S2 = 0.0f, S3 = 0.0f;
    const int4*   k4 = reinterpret_cast<const int4*>(kidx);
    const float4* s4 = reinterpret_cast<const float4*>(ks);

    for (int j4 = 0; j4 < (nk4 >> 2); j4++) {
        int4   ki = k4[j4];                            // broadcast LDS.128
        float4 ss = s4[j4];
        {   float x = *reinterpret_cast<const float*>(srow + swz(rowb + 4u * ki.x));
            float e = __expf(-fabsf(x));
            float num = (x < 0.0f) ? e : 1.0f;
            float sig = num * fast_rcp(1.0f + e);
            float v = ss.x * sig;
            S0 += __expf(v);
            if (v > M) { M = v; jm = 4 * j4 + 0; } }
        {   float x = *reinterpret_cast<const float*>(srow + swz(rowb + 4u * ki.y));
            float e = __expf(-fabsf(x));
            float num = (x < 0.0f) ? e : 1.0f;
            float sig = num * fast_rcp(1.0f + e);
            float v = ss.y * sig;
            S1 += __expf(v);
            if (v > M) { M = v; jm = 4 * j4 + 1; } }
        {   float x = *reinterpret_cast<const float*>(srow + swz(rowb + 4u * ki.z));
            float e = __expf(-fabsf(x));
            float num = (x < 0.0f) ? e : 1.0f;
            float sig = num * fast_rcp(1.0f + e);
            float v = ss.z * sig;
            S2 += __expf(v);
            if (v > M) { M = v; jm = 4 * j4 + 2; } }
        {   float x = *reinterpret_cast<const float*>(srow + swz(rowb + 4u * ki.w));
            float e = __expf(-fabsf(x));
            float num = (x < 0.0f) ? e : 1.0f;
            float sig = num * fast_rcp(1.0f + e);
            float v = ss.w * sig;
            S3 += __expf(v);
            if (v > M) { M = v; jm = 4 * j4 + 3; } }
    }
    float S = (S0 + S1) + (S2 + S3);

    int   mid  = kidx[jm];
    float smid = ks[jm];
    float sig_mid = M * fast_rcp(smid);
    bool validp = active && (nk > 0) && (sig_mid >= 1e-3f) &&
                  (pad[gbase + pc] == 0);

    if (validp) flags[mid] = 1;          // benign race: same value

    if (active) {
        size_t base = gbase + p;
        out[base] = 0.0f;                                               // sem
        out[(size_t)BB * PP + base] = validp ? (float)(mid + 1) : 0.0f; // tmp
        out[(size_t)2 * BB * PP + base] = __expf(M) * fast_rcp(S);      // conf
    }

    __syncthreads();
    // --- Epilogue: flags -> 4 ballot words -> 4 no-return atomics ---------
    {
        bool fp = (t < QQ) ? (flags[t] != 0) : false;
        unsigned word = __ballot_sync(0xffffffffu, fp);
        if (lane == 0 && word) atomicOr(&g_bits[b][wid], word);
    }
}

// ---------------------------------------------------------------------------
// Remap kernel: seg_id(q) = prefix-popcount of g_bits. No scan loops —
// 1 smem broadcast of 8 words + ~5 ALU per element. Output float4 load
// issued first so DRAM latency hides behind the (tiny) setup.
// ---------------------------------------------------------------------------
__global__ void __launch_bounds__(256) remap_kernel(float* __restrict__ out) {
    __shared__ unsigned sw[BB][4];
    __shared__ int      sp[BB][4];     // exclusive word-prefix popcounts
    const int t = threadIdx.x;
    const int i = blockIdx.x * 256 + t;                // one float4 per thread
    const int i0 = i * 4;
    const bool act = (i0 < BB * PP);
    float4* p4 = reinterpret_cast<float4*>(out + (size_t)BB * PP) + i;
    float4 v = make_float4(0.f, 0.f, 0.f, 0.f);
    if (act) v = *p4;                                  // in flight during setup

    if (t < BB * 4) sw[t >> 2][t & 3] = g_bits[t >> 2][t & 3];
    __syncthreads();
    if (t < BB) {
        int run = 0;
        #pragma unroll
        for (int w = 0; w < 4; w++) { sp[t][w] = run; run += __popc(sw[t][w]); }
    }
    __syncthreads();

    if (act) {
        const int b = (i0 >= PP) ? 1 : 0;              // PP % 4 == 0
        float r[4] = {v.x, v.y, v.z, v.w};
        #pragma unroll
        for (int e = 0; e < 4; e++) {
            if (r[e] != 0.0f) {
                int q = (int)r[e] - 1;                 // winning query index
                int w = q >> 5;
                unsigned m = sw[b][w] & (0xffffffffu >> (31 - (q & 31)));
                r[e] = (float)(sp[b][w] + __popc(m));  // inclusive prefix
            }
        }
        *p4 = make_float4(r[0], r[1], r[2], r[3]);
    }
}

extern "C" void kernel_launch(void* const* d_in, const int* in_sizes, int n_in,
                              void* d_out, int out_size) {
    const float* logits = (const float*)d_in[0];
    const float* masks  = (const float*)d_in[1];
    const unsigned char* pad = (const unsigned char*)d_in[2];
    float* out = (float*)d_out;

    static bool attr_set = false;
    if (!attr_set) {
        cudaFuncSetAttribute(main_kernel,
                             cudaFuncAttributeMaxDynamicSharedMemorySize,
                             TILE_BYTES);
        attr_set = true;
    }

    // Zero the 32-byte bitmask scratch (memset node, replaces zero_kernel).
    void* bits_ptr = nullptr;
    cudaGetSymbolAddress(&bits_ptr, g_bits);
    cudaMemsetAsync(bits_ptr, 0, sizeof(unsigned) * BB * 4, 0);

    dim3 grid((PP + TILE - 1) / TILE, BB);
    main_kernel<<<grid, TILE, TILE_BYTES>>>(logits, masks, pad, out);

    remap_kernel<<<(BB * PP / 4 + 255) / 256, 256>>>(out);
}